// round 16
// baseline (speedup 1.0000x reference)
#include <cuda_runtime.h>

static constexpr int NB = 128, NT = 1024, ND = 128, NH = 256, NHD = 128;
typedef unsigned long long ull;

// global persistent state
__device__ __align__(16) float g_h0[2][NB * NH];
__device__ __align__(16) float g_h1[2][NB * NH];
__device__ __align__(16) float g_hd0[2][NB * NHD];
__device__ __align__(16) float g_hd1[2][NB * NHD];
__device__ __align__(128) unsigned g_flag[4][32];   // one 128B line per group

__device__ __forceinline__ void fma2(ull &acc, ull a, ull b) {
    asm("fma.rn.f32x2 %0, %1, %2, %0;" : "+l"(acc) : "l"(a), "l"(b));
}
__device__ __forceinline__ float hadd2(ull v) {
    float lo, hi;
    asm("mov.b64 {%0, %1}, %2;" : "=f"(lo), "=f"(hi) : "l"(v));
    return lo + hi;
}
__device__ __forceinline__ float tanha(float x) {
    float r; asm("tanh.approx.f32 %0, %1;" : "=f"(r) : "f"(x)); return r;
}
__device__ __forceinline__ float siga(float z) {
    return fmaf(0.5f, tanha(0.5f * z), 0.5f);
}
__device__ __forceinline__ float4 ldcg4(const float* p) {
    float4 v;
    asm volatile("ld.global.cg.v4.f32 {%0,%1,%2,%3}, [%4];"
                 : "=f"(v.x), "=f"(v.y), "=f"(v.z), "=f"(v.w) : "l"(p));
    return v;
}
__device__ __forceinline__ void st_rel(unsigned* p, unsigned v) {
    asm volatile("st.release.gpu.global.u32 [%0], %1;" :: "l"(p), "r"(v) : "memory");
}
__device__ __forceinline__ unsigned ld_acq(const unsigned* p) {
    unsigned v;
    asm volatile("ld.acquire.gpu.global.u32 %0, [%1];" : "=r"(v) : "l"(p) : "memory");
    return v;
}
// parallel group barrier wait: warp 0 polls all 32 flags at once
__device__ __forceinline__ void group_wait(unsigned* flags, unsigned ep, int tid) {
    if (tid < 32) {
        unsigned v;
        do { v = ld_acq(&flags[tid]); } while (!__all_sync(0xffffffffu, v >= ep));
    }
}

__global__ void init_state_kernel() {
    int i = blockIdx.x * blockDim.x + threadIdx.x;   // 65536 threads
    ((float*)g_h0)[i] = 0.f;
    ((float*)g_h1)[i] = 0.f;
    if (i < 2 * NB * NHD) { ((float*)g_hd0)[i] = 0.f; ((float*)g_hd1)[i] = 0.f; }
    if (i < 128) ((unsigned*)g_flag)[i] = 0u;
}

// dot block (round-12 engine): thread rows rb+4*ri, 4 batch, LDS:FFMA2 = 0.25
template<int NJ, int CS, int WS, int AS>
__device__ __forceinline__ void dotblk(const float* __restrict__ wb,
                                       const float* __restrict__ ab,
                                       int rb, int bs, int khb,
                                       ull (&acc)[4][4])
{
#pragma unroll
    for (int j = 0; j < NJ; j++) {
        int c = CS * j + khb;
        ulonglong2 a0 = *(const ulonglong2*)&ab[(bs +  0) * AS + c];
        ulonglong2 a1 = *(const ulonglong2*)&ab[(bs +  8) * AS + c];
        ulonglong2 a2 = *(const ulonglong2*)&ab[(bs + 16) * AS + c];
        ulonglong2 a3 = *(const ulonglong2*)&ab[(bs + 24) * AS + c];
#pragma unroll
        for (int ri = 0; ri < 4; ri++) {
            ulonglong2 w = *(const ulonglong2*)&wb[(rb + 4 * ri) * WS + c];
            fma2(acc[ri][0], a0.x, w.x); fma2(acc[ri][0], a0.y, w.y);
            fma2(acc[ri][1], a1.x, w.x); fma2(acc[ri][1], a1.y, w.y);
            fma2(acc[ri][2], a2.x, w.x); fma2(acc[ri][2], a2.y, w.y);
            fma2(acc[ri][3], a3.x, w.x); fma2(acc[ri][3], a3.y, w.y);
        }
    }
}

// SMEM float offsets (encoder region)
#define E_W0X 0
#define E_W0H 4224
#define E_W1I 12544
#define E_W1H 20864
#define E_XS  29184
#define E_H0P 33408
#define E_H1P 41728
#define E_PRE 50048   /* [2 banks][2 L][32][36]; bank stride 2304, L stride 1152 */
#define E_CST 54656   /* [2][256] */
#define E_BIA 55168   /* [64] */
#define E_TOT 55232
// SMEM float offsets (decoder region, reuses same dynamic SMEM)
#define D_W0H 0
#define D_W1I 2112
#define D_W1H 4224
#define D_H0P 6336
#define D_H1P 10560
#define D_XW  14784   /* [32][17] */
#define D_PRE 15328   /* [4 banks][2 L][16][40]; bank stride 1280, L stride 640 */
#define D_CST 20448   /* [2][128] */
#define D_BIA 20704   /* [16] */
#define D_TOT 20720

// =================== single fused persistent kernel ===================
__global__ void __launch_bounds__(512, 1) lstm_persist(
    const float* __restrict__ x,
    const float* __restrict__ eW0, const float* __restrict__ eU0,
    const float* __restrict__ eb0, const float* __restrict__ ec0,
    const float* __restrict__ eW1, const float* __restrict__ eU1,
    const float* __restrict__ eb1, const float* __restrict__ ec1,
    const float* __restrict__ dW0, const float* __restrict__ dU0,
    const float* __restrict__ db0, const float* __restrict__ dc0,
    const float* __restrict__ dW1, const float* __restrict__ dU1,
    const float* __restrict__ db1, const float* __restrict__ dc1,
    float* __restrict__ out)
{
    extern __shared__ float sm[];
    const int tid = threadIdx.x;
    const int grp = blockIdx.x >> 5;
    const int cta = blockIdx.x & 31;
    const int bg  = grp * 32;
    unsigned* flags = g_flag[grp];
    unsigned ep = 0;

    // ================= ENCODER =================
    {
        const int ub = cta * 8;
        for (int idx = tid; idx < 32 * 128; idx += 512) {
            int row = idx >> 7, k = idx & 127;
            int grow = (row >> 3) * NH + ub + (row & 7);
            sm[E_W0X + row * 132 + k] = eW0[grow * ND + k];
        }
        for (int idx = tid; idx < 32 * 256; idx += 512) {
            int row = idx >> 8, k = idx & 255;
            int grow = (row >> 3) * NH + ub + (row & 7);
            sm[E_W0H + row * 260 + k] = eU0[grow * NH + k];
            sm[E_W1I + row * 260 + k] = eW1[grow * NH + k];
            sm[E_W1H + row * 260 + k] = eU1[grow * NH + k];
        }
        if (tid < 32) {
            int grow = (tid >> 3) * NH + ub + (tid & 7);
            sm[E_BIA + tid]      = eb0[grow] + ec0[grow];
            sm[E_BIA + 32 + tid] = eb1[grow] + ec1[grow];
        }
        for (int idx = tid; idx < 512; idx += 512) sm[E_CST + idx] = 0.f;

        // prologue staging: x(0) + zeroed h
        for (int idx = tid; idx < 32 * 32; idx += 512) {
            int row = idx >> 5, c4 = (idx & 31) << 2;
            *(float4*)&sm[E_XS + row * 132 + c4] =
                __ldg((const float4*)&x[((bg + row) * NT + 0) * ND + c4]);
        }
        {
            const float* h0g = g_h0[1];
            const float* h1g = g_h1[0];
            for (int idx = tid; idx < 32 * 64; idx += 512) {
                int row = idx >> 6, c4 = (idx & 63) << 2;
                *(float4*)&sm[E_H0P + row * 260 + c4] = ldcg4(&h0g[(bg + row) * NH + c4]);
                *(float4*)&sm[E_H1P + row * 260 + c4] = ldcg4(&h1g[(bg + row) * NH + c4]);
            }
        }
        __syncthreads();

        const int L   = tid >> 8;
        const int t   = tid & 255;
        const int bs  = t & 7;
        const int rgl = (t >> 3) & 3;
        const int kh  = (t >> 5) & 3;
        const int rgh = t >> 7;
        const int rb  = rgh * 16 + rgl;    // rows rb, rb+4, rb+8, rb+12
        const int khb = 4 * kh;

        ull acc[4][4] = {};
        // prologue: L0 x-part for step 0
        if (L == 0)
            dotblk< 8, 16, 132, 132>(sm + E_W0X, sm + E_XS, rb, bs, khb, acc);

        for (int s = 0; s <= NT; s++) {
            const bool act = (L == 0) ? (s < NT) : (s >= 1);
            if (L == 0) {
                if (act)
                    dotblk<16, 16, 260, 260>(sm + E_W0H, sm + E_H0P, rb, bs, khb, acc);
            } else {
#pragma unroll
                for (int ri = 0; ri < 4; ri++)
#pragma unroll
                    for (int i = 0; i < 4; i++) acc[ri][i] = 0ULL;
                if (act) {
                    dotblk<16, 16, 260, 260>(sm + E_W1I, sm + E_H0P, rb, bs, khb, acc);
                    dotblk<16, 16, 260, 260>(sm + E_W1H, sm + E_H1P, rb, bs, khb, acc);
                }
            }
            // two-phase merge into pre banks
            float* pb = sm + E_PRE + (kh & 1) * 2304 + L * 1152;
            if (act && (kh >> 1) == 0) {
#pragma unroll
                for (int ri = 0; ri < 4; ri++)
#pragma unroll
                    for (int i = 0; i < 4; i++)
                        pb[(rb + 4 * ri) * 36 + bs + 8 * i] = hadd2(acc[ri][i]);
            }
            __syncthreads();
            if (act && (kh >> 1) == 1) {
#pragma unroll
                for (int ri = 0; ri < 4; ri++)
#pragma unroll
                    for (int i = 0; i < 4; i++)
                        pb[(rb + 4 * ri) * 36 + bs + 8 * i] += hadd2(acc[ri][i]);
            }
            __syncthreads();

            // combine + state update (SMEM cell state, exactly as round 12)
            {
                const int cl = tid >> 8, u = tid & 7, b = (tid >> 3) & 31;
                bool ok = (cl == 0) ? (s < NT) : (s >= 1);
                if (ok) {
                    const float* pa = sm + E_PRE + cl * 1152;
                    const float* pc = pa + 2304;
                    float gi = pa[(0*8+u)*36 + b] + pc[(0*8+u)*36 + b] + sm[E_BIA + cl*32 + 0*8 + u];
                    float gf = pa[(1*8+u)*36 + b] + pc[(1*8+u)*36 + b] + sm[E_BIA + cl*32 + 1*8 + u];
                    float gg = pa[(2*8+u)*36 + b] + pc[(2*8+u)*36 + b] + sm[E_BIA + cl*32 + 2*8 + u];
                    float go = pa[(3*8+u)*36 + b] + pc[(3*8+u)*36 + b] + sm[E_BIA + cl*32 + 3*8 + u];
                    float c  = sm[E_CST + cl * 256 + b * 8 + u];
                    float cv = siga(gf) * c + siga(gi) * tanha(gg);
                    sm[E_CST + cl * 256 + b * 8 + u] = cv;
                    float hv = siga(go) * tanha(cv);
                    int gidx = (bg + b) * NH + ub + u;
                    if (cl == 0) g_h0[s & 1][gidx] = hv;
                    else         g_h1[(s - 1) & 1][gidx] = hv;
                }
            }
            __syncthreads();
            if (s == NT) break;

            // arrive (flag); overlap x staging; parallel poll; stage h
            ep++;
            if (tid == 0) st_rel(&flags[cta], ep);
            if (s + 1 < NT) {
                for (int idx = tid; idx < 32 * 32; idx += 512) {
                    int row = idx >> 5, c4 = (idx & 31) << 2;
                    *(float4*)&sm[E_XS + row * 132 + c4] =
                        __ldg((const float4*)&x[((bg + row) * NT + (s + 1)) * ND + c4]);
                }
            }
            group_wait(flags, ep, tid);
            __syncthreads();
            if (L == 0) {
#pragma unroll
                for (int ri = 0; ri < 4; ri++)
#pragma unroll
                    for (int i = 0; i < 4; i++) acc[ri][i] = 0ULL;
                if (s + 1 < NT)
                    dotblk< 8, 16, 132, 132>(sm + E_W0X, sm + E_XS, rb, bs, khb, acc);
            } else {
                const float* h0g = g_h0[s & 1];
                const float* h1g = g_h1[(s + 1) & 1];
                for (int idx = tid - 256; idx < 32 * 64; idx += 256) {
                    int row = idx >> 6, c4 = (idx & 63) << 2;
                    *(float4*)&sm[E_H0P + row * 260 + c4] = ldcg4(&h0g[(bg + row) * NH + c4]);
                    *(float4*)&sm[E_H1P + row * 260 + c4] = ldcg4(&h1g[(bg + row) * NH + c4]);
                }
            }
            __syncthreads();
        }
    }

    // group barrier: all CTAs finished encoder (final g_h1 visible)
    ep++;
    if (tid == 0) st_rel(&flags[cta], ep);
    group_wait(flags, ep, tid);
    __syncthreads();

    // ================= DECODER =================
    {
        const int ub = cta * 4;
        for (int idx = tid; idx < 16 * 128; idx += 512) {
            int row = idx >> 7, k = idx & 127;
            int grow = (row >> 2) * NHD + ub + (row & 3);
            sm[D_W0H + row * 132 + k] = dU0[grow * NHD + k];
            sm[D_W1I + row * 132 + k] = dW1[grow * NHD + k];
            sm[D_W1H + row * 132 + k] = dU1[grow * NHD + k];
        }
        if (tid < 16) {
            int grow = (tid >> 2) * NHD + ub + (tid & 3);
            sm[D_BIA + tid] = db1[grow] + dc1[grow];
        }
        {   // xwd0 slice: one (b,row) per thread
            int b = tid >> 4, row = tid & 15;
            int grow = (row >> 2) * NHD + ub + (row & 3);
            const float* hb = &g_h1[1][(bg + b) * NH];
            const float* wr = dW0 + grow * NH;
            ull a0 = 0ULL, a1 = 0ULL;
#pragma unroll 4
            for (int k = 0; k < NH; k += 4) {
                float4 hv = ldcg4(&hb[k]);
                ulonglong2 h2; h2.x = *(const ull*)&hv.x; h2.y = *(const ull*)&hv.z;
                ulonglong2 wv = *(const ulonglong2*)&wr[k];
                fma2(a0, h2.x, wv.x); fma2(a1, h2.y, wv.y);
            }
            sm[D_XW + b * 17 + row] = hadd2(a0) + hadd2(a1) + db0[grow] + dc0[grow];
        }
        for (int idx = tid; idx < 256; idx += 512) sm[D_CST + idx] = 0.f;
        {
            const float* h0g = g_hd0[1];
            const float* h1g = g_hd1[0];
            for (int idx = tid; idx < 32 * 32; idx += 512) {
                int row = idx >> 5, c4 = (idx & 31) << 2;
                *(float4*)&sm[D_H0P + row * 132 + c4] = ldcg4(&h0g[(bg + row) * NHD + c4]);
                *(float4*)&sm[D_H1P + row * 132 + c4] = ldcg4(&h1g[(bg + row) * NHD + c4]);
            }
        }
        __syncthreads();

        const int L   = tid >> 8;
        const int t   = tid & 255;
        const int bs  = t & 7;
        const int rb  = (t >> 3) & 3;      // rows rb, rb+4, rb+8, rb+12
        const int kh  = t >> 5;            // 0..7
        const int khb = 4 * kh;

        for (int s = 0; s <= NT; s++) {
            const bool act = (L == 0) ? (s < NT) : (s >= 1);
            ull acc[4][4] = {};
            if (act) {
                if (L == 0) {
                    dotblk<4, 32, 132, 132>(sm + D_W0H, sm + D_H0P, rb, bs, khb, acc);
                } else {
                    dotblk<4, 32, 132, 132>(sm + D_W1I, sm + D_H0P, rb, bs, khb, acc);
                    dotblk<4, 32, 132, 132>(sm + D_W1H, sm + D_H1P, rb, bs, khb, acc);
                }
            }
            float* pb = sm + D_PRE + (kh & 3) * 1280 + L * 640;
            if (act && (kh >> 2) == 0) {
#pragma unroll
                for (int ri = 0; ri < 4; ri++)
#pragma unroll
                    for (int i = 0; i < 4; i++)
                        pb[(rb + 4 * ri) * 40 + bs + 8 * i] = hadd2(acc[ri][i]);
            }
            __syncthreads();
            if (act && (kh >> 2) == 1) {
#pragma unroll
                for (int ri = 0; ri < 4; ri++)
#pragma unroll
                    for (int i = 0; i < 4; i++)
                        pb[(rb + 4 * ri) * 40 + bs + 8 * i] += hadd2(acc[ri][i]);
            }
            __syncthreads();

            if (tid < 256) {
                const int cl = tid >> 7, u = tid & 3, b = (tid >> 2) & 31;
                bool ok = (cl == 0) ? (s < NT) : (s >= 1);
                if (ok) {
                    float g4[4];
#pragma unroll
                    for (int g = 0; g < 4; g++) {
                        int r = g * 4 + u;
                        float v = sm[D_PRE + 0 * 1280 + cl * 640 + r * 40 + b]
                                + sm[D_PRE + 1 * 1280 + cl * 640 + r * 40 + b]
                                + sm[D_PRE + 2 * 1280 + cl * 640 + r * 40 + b]
                                + sm[D_PRE + 3 * 1280 + cl * 640 + r * 40 + b];
                        v += (cl == 0) ? sm[D_XW + b * 17 + r] : sm[D_BIA + r];
                        g4[g] = v;
                    }
                    float c  = sm[D_CST + cl * 128 + b * 4 + u];
                    float cv = siga(g4[1]) * c + siga(g4[0]) * tanha(g4[2]);
                    sm[D_CST + cl * 128 + b * 4 + u] = cv;
                    float hv = siga(g4[3]) * tanha(cv);
                    int gidx = (bg + b) * NHD + ub + u;
                    if (cl == 0) g_hd0[s & 1][gidx] = hv;
                    else {
                        g_hd1[(s - 1) & 1][gidx] = hv;
                        out[((bg + b) * NT + (s - 1)) * ND + ub + u] = hv;
                    }
                }
            }
            __syncthreads();
            if (s == NT) break;

            ep++;
            if (tid == 0) st_rel(&flags[cta], ep);
            group_wait(flags, ep, tid);
            __syncthreads();
            {
                const float* h0g = g_hd0[s & 1];
                const float* h1g = g_hd1[(s + 1) & 1];
                for (int idx = tid; idx < 32 * 32; idx += 512) {
                    int row = idx >> 5, c4 = (idx & 31) << 2;
                    *(float4*)&sm[D_H0P + row * 132 + c4] = ldcg4(&h0g[(bg + row) * NHD + c4]);
                    *(float4*)&sm[D_H1P + row * 132 + c4] = ldcg4(&h1g[(bg + row) * NHD + c4]);
                }
            }
            __syncthreads();
        }
    }
}

extern "C" void kernel_launch(void* const* d_in, const int* in_sizes, int n_in,
                              void* d_out, int out_size)
{
    (void)in_sizes; (void)n_in; (void)out_size;
    const float* x   = (const float*)d_in[0];
    const float* eW0 = (const float*)d_in[1];
    const float* eU0 = (const float*)d_in[2];
    const float* eb0 = (const float*)d_in[3];
    const float* ec0 = (const float*)d_in[4];
    const float* eW1 = (const float*)d_in[5];
    const float* eU1 = (const float*)d_in[6];
    const float* eb1 = (const float*)d_in[7];
    const float* ec1 = (const float*)d_in[8];
    const float* dW0 = (const float*)d_in[9];
    const float* dU0 = (const float*)d_in[10];
    const float* db0 = (const float*)d_in[11];
    const float* dc0 = (const float*)d_in[12];
    const float* dW1 = (const float*)d_in[13];
    const float* dU1 = (const float*)d_in[14];
    const float* db1 = (const float*)d_in[15];
    const float* dc1 = (const float*)d_in[16];
    float* out = (float*)d_out;

    const int SMEM = E_TOT * 4;   // 220928 B

    static bool attr_done = false;
    if (!attr_done) {
        cudaFuncSetAttribute(lstm_persist, cudaFuncAttributeMaxDynamicSharedMemorySize, SMEM);
        attr_done = true;
    }

    init_state_kernel<<<128, 512>>>();
    lstm_persist<<<128, 512, SMEM>>>(x, eW0, eU0, eb0, ec0, eW1, eU1, eb1, ec1,
                                     dW0, dU0, db0, dc0, dW1, dU1, db1, dc1, out);
}

// round 17
// speedup vs baseline: 1.4018x; 1.4018x over previous
#include <cuda_runtime.h>

static constexpr int NB = 128, NT = 1024, ND = 128, NH = 256, NHD = 128;
typedef unsigned long long ull;

// global persistent state
__device__ __align__(16) float g_h0[2][NB * NH];
__device__ __align__(16) float g_h1[2][NB * NH];
__device__ __align__(16) float g_hd0[2][NB * NHD];
__device__ __align__(16) float g_hd1[2][NB * NHD];
// 4 sub-counters per group, each on its own 128B line
__device__ __align__(128) unsigned g_bar[4][4][32];

__device__ __forceinline__ void fma2(ull &acc, ull a, ull b) {
    asm("fma.rn.f32x2 %0, %1, %2, %0;" : "+l"(acc) : "l"(a), "l"(b));
}
__device__ __forceinline__ float hadd2(ull v) {
    float lo, hi;
    asm("mov.b64 {%0, %1}, %2;" : "=f"(lo), "=f"(hi) : "l"(v));
    return lo + hi;
}
__device__ __forceinline__ float tanha(float x) {
    float r; asm("tanh.approx.f32 %0, %1;" : "=f"(r) : "f"(x)); return r;
}
__device__ __forceinline__ float siga(float z) {
    return fmaf(0.5f, tanha(0.5f * z), 0.5f);
}
__device__ __forceinline__ float4 ldcg4(const float* p) {
    float4 v;
    asm volatile("ld.global.cg.v4.f32 {%0,%1,%2,%3}, [%4];"
                 : "=f"(v.x), "=f"(v.y), "=f"(v.z), "=f"(v.w) : "l"(p));
    return v;
}
__device__ __forceinline__ void bar_arrive(unsigned* p) {
    asm volatile("red.release.gpu.global.add.u32 [%0], 1;" :: "l"(p) : "memory");
}
__device__ __forceinline__ unsigned ld_acq(const unsigned* p) {
    unsigned v;
    asm volatile("ld.acquire.gpu.global.u32 %0, [%1];" : "=r"(v) : "l"(p) : "memory");
    return v;
}
// hierarchical wait: 4 lanes, each polls its own sub-counter (8 arrivals each)
__device__ __forceinline__ void group_wait(unsigned* base, unsigned ep, int tid) {
    if (tid < 4) {
        unsigned tgt = 8u * ep;
        while (ld_acq(base + tid * 32) < tgt) { }
    }
}

__global__ void init_state_kernel() {
    int i = blockIdx.x * blockDim.x + threadIdx.x;   // 65536 threads
    ((float*)g_h0)[i] = 0.f;
    ((float*)g_h1)[i] = 0.f;
    if (i < 2 * NB * NHD) { ((float*)g_hd0)[i] = 0.f; ((float*)g_hd1)[i] = 0.f; }
    if (i < 512) ((unsigned*)g_bar)[i] = 0u;
}

// dot block (round-12 engine): thread rows rb+4*ri, 4 batch, LDS:FFMA2 = 0.25
template<int NJ, int CS, int WS, int AS>
__device__ __forceinline__ void dotblk(const float* __restrict__ wb,
                                       const float* __restrict__ ab,
                                       int rb, int bs, int khb,
                                       ull (&acc)[4][4])
{
#pragma unroll
    for (int j = 0; j < NJ; j++) {
        int c = CS * j + khb;
        ulonglong2 a0 = *(const ulonglong2*)&ab[(bs +  0) * AS + c];
        ulonglong2 a1 = *(const ulonglong2*)&ab[(bs +  8) * AS + c];
        ulonglong2 a2 = *(const ulonglong2*)&ab[(bs + 16) * AS + c];
        ulonglong2 a3 = *(const ulonglong2*)&ab[(bs + 24) * AS + c];
#pragma unroll
        for (int ri = 0; ri < 4; ri++) {
            ulonglong2 w = *(const ulonglong2*)&wb[(rb + 4 * ri) * WS + c];
            fma2(acc[ri][0], a0.x, w.x); fma2(acc[ri][0], a0.y, w.y);
            fma2(acc[ri][1], a1.x, w.x); fma2(acc[ri][1], a1.y, w.y);
            fma2(acc[ri][2], a2.x, w.x); fma2(acc[ri][2], a2.y, w.y);
            fma2(acc[ri][3], a3.x, w.x); fma2(acc[ri][3], a3.y, w.y);
        }
    }
}

// SMEM float offsets (encoder region)
#define E_W0X 0
#define E_W0H 4224
#define E_W1I 12544
#define E_W1H 20864
#define E_XS  29184
#define E_H0P 33408
#define E_H1P 41728
#define E_PRE 50048   /* [2 banks][2 L][32][36]; bank stride 2304, L stride 1152 */
#define E_CST 54656   /* [2][256] */
#define E_BIA 55168   /* [64] */
#define E_TOT 55232
// SMEM float offsets (decoder region, reuses same dynamic SMEM)
#define D_W0H 0
#define D_W1I 2112
#define D_W1H 4224
#define D_H0P 6336
#define D_H1P 10560
#define D_XW  14784   /* [32][17] */
#define D_PRE 15328   /* [4 banks][2 L][16][40]; bank stride 1280, L stride 640 */
#define D_CST 20448   /* [2][128] */
#define D_BIA 20704   /* [16] */
#define D_TOT 20720

// =================== single fused persistent kernel ===================
__global__ void __launch_bounds__(512, 1) lstm_persist(
    const float* __restrict__ x,
    const float* __restrict__ eW0, const float* __restrict__ eU0,
    const float* __restrict__ eb0, const float* __restrict__ ec0,
    const float* __restrict__ eW1, const float* __restrict__ eU1,
    const float* __restrict__ eb1, const float* __restrict__ ec1,
    const float* __restrict__ dW0, const float* __restrict__ dU0,
    const float* __restrict__ db0, const float* __restrict__ dc0,
    const float* __restrict__ dW1, const float* __restrict__ dU1,
    const float* __restrict__ db1, const float* __restrict__ dc1,
    float* __restrict__ out)
{
    extern __shared__ float sm[];
    const int tid = threadIdx.x;
    const int grp = blockIdx.x >> 5;
    const int cta = blockIdx.x & 31;
    const int bg  = grp * 32;
    unsigned* barbase = &g_bar[grp][0][0];
    unsigned* mybar   = &g_bar[grp][cta >> 3][0];
    unsigned ep = 0;

    // ================= ENCODER =================
    {
        const int ub = cta * 8;
        for (int idx = tid; idx < 32 * 128; idx += 512) {
            int row = idx >> 7, k = idx & 127;
            int grow = (row >> 3) * NH + ub + (row & 7);
            sm[E_W0X + row * 132 + k] = eW0[grow * ND + k];
        }
        for (int idx = tid; idx < 32 * 256; idx += 512) {
            int row = idx >> 8, k = idx & 255;
            int grow = (row >> 3) * NH + ub + (row & 7);
            sm[E_W0H + row * 260 + k] = eU0[grow * NH + k];
            sm[E_W1I + row * 260 + k] = eW1[grow * NH + k];
            sm[E_W1H + row * 260 + k] = eU1[grow * NH + k];
        }
        if (tid < 32) {
            int grow = (tid >> 3) * NH + ub + (tid & 7);
            sm[E_BIA + tid]      = eb0[grow] + ec0[grow];
            sm[E_BIA + 32 + tid] = eb1[grow] + ec1[grow];
        }
        for (int idx = tid; idx < 512; idx += 512) sm[E_CST + idx] = 0.f;

        // prologue staging: x(0) + zeroed h
        for (int idx = tid; idx < 32 * 32; idx += 512) {
            int row = idx >> 5, c4 = (idx & 31) << 2;
            *(float4*)&sm[E_XS + row * 132 + c4] =
                __ldg((const float4*)&x[((bg + row) * NT + 0) * ND + c4]);
        }
        {
            const float* h0g = g_h0[1];
            const float* h1g = g_h1[0];
            for (int idx = tid; idx < 32 * 64; idx += 512) {
                int row = idx >> 6, c4 = (idx & 63) << 2;
                *(float4*)&sm[E_H0P + row * 260 + c4] = ldcg4(&h0g[(bg + row) * NH + c4]);
                *(float4*)&sm[E_H1P + row * 260 + c4] = ldcg4(&h1g[(bg + row) * NH + c4]);
            }
        }
        __syncthreads();

        const int L   = tid >> 8;
        const int t   = tid & 255;
        const int bs  = t & 7;
        const int rgl = (t >> 3) & 3;
        const int kh  = (t >> 5) & 3;
        const int rgh = t >> 7;
        const int rb  = rgh * 16 + rgl;    // rows rb, rb+4, rb+8, rb+12
        const int khb = 4 * kh;

        ull acc[4][4] = {};
        // prologue: L0 x-part for step 0
        if (L == 0)
            dotblk< 8, 16, 132, 132>(sm + E_W0X, sm + E_XS, rb, bs, khb, acc);

        for (int s = 0; s <= NT; s++) {
            const bool act = (L == 0) ? (s < NT) : (s >= 1);
            if (L == 0) {
                if (act)
                    dotblk<16, 16, 260, 260>(sm + E_W0H, sm + E_H0P, rb, bs, khb, acc);
            } else {
#pragma unroll
                for (int ri = 0; ri < 4; ri++)
#pragma unroll
                    for (int i = 0; i < 4; i++) acc[ri][i] = 0ULL;
                if (act) {
                    dotblk<16, 16, 260, 260>(sm + E_W1I, sm + E_H0P, rb, bs, khb, acc);
                    dotblk<16, 16, 260, 260>(sm + E_W1H, sm + E_H1P, rb, bs, khb, acc);
                }
            }
            // two-phase merge into pre banks
            float* pb = sm + E_PRE + (kh & 1) * 2304 + L * 1152;
            if (act && (kh >> 1) == 0) {
#pragma unroll
                for (int ri = 0; ri < 4; ri++)
#pragma unroll
                    for (int i = 0; i < 4; i++)
                        pb[(rb + 4 * ri) * 36 + bs + 8 * i] = hadd2(acc[ri][i]);
            }
            __syncthreads();
            if (act && (kh >> 1) == 1) {
#pragma unroll
                for (int ri = 0; ri < 4; ri++)
#pragma unroll
                    for (int i = 0; i < 4; i++)
                        pb[(rb + 4 * ri) * 36 + bs + 8 * i] += hadd2(acc[ri][i]);
            }
            __syncthreads();

            // combine + state update (SMEM cell state, as round 12)
            {
                const int cl = tid >> 8, u = tid & 7, b = (tid >> 3) & 31;
                bool ok = (cl == 0) ? (s < NT) : (s >= 1);
                if (ok) {
                    const float* pa = sm + E_PRE + cl * 1152;
                    const float* pc = pa + 2304;
                    float gi = pa[(0*8+u)*36 + b] + pc[(0*8+u)*36 + b] + sm[E_BIA + cl*32 + 0*8 + u];
                    float gf = pa[(1*8+u)*36 + b] + pc[(1*8+u)*36 + b] + sm[E_BIA + cl*32 + 1*8 + u];
                    float gg = pa[(2*8+u)*36 + b] + pc[(2*8+u)*36 + b] + sm[E_BIA + cl*32 + 2*8 + u];
                    float go = pa[(3*8+u)*36 + b] + pc[(3*8+u)*36 + b] + sm[E_BIA + cl*32 + 3*8 + u];
                    float c  = sm[E_CST + cl * 256 + b * 8 + u];
                    float cv = siga(gf) * c + siga(gi) * tanha(gg);
                    sm[E_CST + cl * 256 + b * 8 + u] = cv;
                    float hv = siga(go) * tanha(cv);
                    int gidx = (bg + b) * NH + ub + u;
                    if (cl == 0) g_h0[s & 1][gidx] = hv;
                    else         g_h1[(s - 1) & 1][gidx] = hv;
                }
            }
            __syncthreads();
            if (s == NT) break;

            // arrive (sub-counter); overlap x staging; 4-lane poll; stage h
            ep++;
            if (tid == 0) bar_arrive(mybar);
            if (s + 1 < NT) {
                for (int idx = tid; idx < 32 * 32; idx += 512) {
                    int row = idx >> 5, c4 = (idx & 31) << 2;
                    *(float4*)&sm[E_XS + row * 132 + c4] =
                        __ldg((const float4*)&x[((bg + row) * NT + (s + 1)) * ND + c4]);
                }
            }
            group_wait(barbase, ep, tid);
            __syncthreads();
            if (L == 0) {
#pragma unroll
                for (int ri = 0; ri < 4; ri++)
#pragma unroll
                    for (int i = 0; i < 4; i++) acc[ri][i] = 0ULL;
                if (s + 1 < NT)
                    dotblk< 8, 16, 132, 132>(sm + E_W0X, sm + E_XS, rb, bs, khb, acc);
            } else {
                const float* h0g = g_h0[s & 1];
                const float* h1g = g_h1[(s + 1) & 1];
                for (int idx = tid - 256; idx < 32 * 64; idx += 256) {
                    int row = idx >> 6, c4 = (idx & 63) << 2;
                    *(float4*)&sm[E_H0P + row * 260 + c4] = ldcg4(&h0g[(bg + row) * NH + c4]);
                    *(float4*)&sm[E_H1P + row * 260 + c4] = ldcg4(&h1g[(bg + row) * NH + c4]);
                }
            }
            __syncthreads();
        }
    }

    // group barrier: all CTAs finished encoder (final g_h1 visible)
    ep++;
    if (tid == 0) bar_arrive(mybar);
    group_wait(barbase, ep, tid);
    __syncthreads();

    // ================= DECODER =================
    {
        const int ub = cta * 4;
        for (int idx = tid; idx < 16 * 128; idx += 512) {
            int row = idx >> 7, k = idx & 127;
            int grow = (row >> 2) * NHD + ub + (row & 3);
            sm[D_W0H + row * 132 + k] = dU0[grow * NHD + k];
            sm[D_W1I + row * 132 + k] = dW1[grow * NHD + k];
            sm[D_W1H + row * 132 + k] = dU1[grow * NHD + k];
        }
        if (tid < 16) {
            int grow = (tid >> 2) * NHD + ub + (tid & 3);
            sm[D_BIA + tid] = db1[grow] + dc1[grow];
        }
        {   // xwd0 slice: one (b,row) per thread
            int b = tid >> 4, row = tid & 15;
            int grow = (row >> 2) * NHD + ub + (row & 3);
            const float* hb = &g_h1[1][(bg + b) * NH];
            const float* wr = dW0 + grow * NH;
            ull a0 = 0ULL, a1 = 0ULL;
#pragma unroll 4
            for (int k = 0; k < NH; k += 4) {
                float4 hv = ldcg4(&hb[k]);
                ulonglong2 h2; h2.x = *(const ull*)&hv.x; h2.y = *(const ull*)&hv.z;
                ulonglong2 wv = *(const ulonglong2*)&wr[k];
                fma2(a0, h2.x, wv.x); fma2(a1, h2.y, wv.y);
            }
            sm[D_XW + b * 17 + row] = hadd2(a0) + hadd2(a1) + db0[grow] + dc0[grow];
        }
        for (int idx = tid; idx < 256; idx += 512) sm[D_CST + idx] = 0.f;
        {
            const float* h0g = g_hd0[1];
            const float* h1g = g_hd1[0];
            for (int idx = tid; idx < 32 * 32; idx += 512) {
                int row = idx >> 5, c4 = (idx & 31) << 2;
                *(float4*)&sm[D_H0P + row * 132 + c4] = ldcg4(&h0g[(bg + row) * NHD + c4]);
                *(float4*)&sm[D_H1P + row * 132 + c4] = ldcg4(&h1g[(bg + row) * NHD + c4]);
            }
        }
        __syncthreads();

        const int L   = tid >> 8;
        const int t   = tid & 255;
        const int bs  = t & 7;
        const int rb  = (t >> 3) & 3;      // rows rb, rb+4, rb+8, rb+12
        const int kh  = t >> 5;            // 0..7
        const int khb = 4 * kh;

        for (int s = 0; s <= NT; s++) {
            const bool act = (L == 0) ? (s < NT) : (s >= 1);
            ull acc[4][4] = {};
            if (act) {
                if (L == 0) {
                    dotblk<4, 32, 132, 132>(sm + D_W0H, sm + D_H0P, rb, bs, khb, acc);
                } else {
                    dotblk<4, 32, 132, 132>(sm + D_W1I, sm + D_H0P, rb, bs, khb, acc);
                    dotblk<4, 32, 132, 132>(sm + D_W1H, sm + D_H1P, rb, bs, khb, acc);
                }
            }
            float* pb = sm + D_PRE + (kh & 3) * 1280 + L * 640;
            if (act && (kh >> 2) == 0) {
#pragma unroll
                for (int ri = 0; ri < 4; ri++)
#pragma unroll
                    for (int i = 0; i < 4; i++)
                        pb[(rb + 4 * ri) * 40 + bs + 8 * i] = hadd2(acc[ri][i]);
            }
            __syncthreads();
            if (act && (kh >> 2) == 1) {
#pragma unroll
                for (int ri = 0; ri < 4; ri++)
#pragma unroll
                    for (int i = 0; i < 4; i++)
                        pb[(rb + 4 * ri) * 40 + bs + 8 * i] += hadd2(acc[ri][i]);
            }
            __syncthreads();

            if (tid < 256) {
                const int cl = tid >> 7, u = tid & 3, b = (tid >> 2) & 31;
                bool ok = (cl == 0) ? (s < NT) : (s >= 1);
                if (ok) {
                    float g4[4];
#pragma unroll
                    for (int g = 0; g < 4; g++) {
                        int r = g * 4 + u;
                        float v = sm[D_PRE + 0 * 1280 + cl * 640 + r * 40 + b]
                                + sm[D_PRE + 1 * 1280 + cl * 640 + r * 40 + b]
                                + sm[D_PRE + 2 * 1280 + cl * 640 + r * 40 + b]
                                + sm[D_PRE + 3 * 1280 + cl * 640 + r * 40 + b];
                        v += (cl == 0) ? sm[D_XW + b * 17 + r] : sm[D_BIA + r];
                        g4[g] = v;
                    }
                    float c  = sm[D_CST + cl * 128 + b * 4 + u];
                    float cv = siga(g4[1]) * c + siga(g4[0]) * tanha(g4[2]);
                    sm[D_CST + cl * 128 + b * 4 + u] = cv;
                    float hv = siga(g4[3]) * tanha(cv);
                    int gidx = (bg + b) * NHD + ub + u;
                    if (cl == 0) g_hd0[s & 1][gidx] = hv;
                    else {
                        g_hd1[(s - 1) & 1][gidx] = hv;
                        out[((bg + b) * NT + (s - 1)) * ND + ub + u] = hv;
                    }
                }
            }
            __syncthreads();
            if (s == NT) break;

            ep++;
            if (tid == 0) bar_arrive(mybar);
            group_wait(barbase, ep, tid);
            __syncthreads();
            {
                const float* h0g = g_hd0[s & 1];
                const float* h1g = g_hd1[(s + 1) & 1];
                for (int idx = tid; idx < 32 * 32; idx += 512) {
                    int row = idx >> 5, c4 = (idx & 31) << 2;
                    *(float4*)&sm[D_H0P + row * 132 + c4] = ldcg4(&h0g[(bg + row) * NHD + c4]);
                    *(float4*)&sm[D_H1P + row * 132 + c4] = ldcg4(&h1g[(bg + row) * NHD + c4]);
                }
            }
            __syncthreads();
        }
    }
}

extern "C" void kernel_launch(void* const* d_in, const int* in_sizes, int n_in,
                              void* d_out, int out_size)
{
    (void)in_sizes; (void)n_in; (void)out_size;
    const float* x   = (const float*)d_in[0];
    const float* eW0 = (const float*)d_in[1];
    const float* eU0 = (const float*)d_in[2];
    const float* eb0 = (const float*)d_in[3];
    const float* ec0 = (const float*)d_in[4];
    const float* eW1 = (const float*)d_in[5];
    const float* eU1 = (const float*)d_in[6];
    const float* eb1 = (const float*)d_in[7];
    const float* ec1 = (const float*)d_in[8];
    const float* dW0 = (const float*)d_in[9];
    const float* dU0 = (const float*)d_in[10];
    const float* db0 = (const float*)d_in[11];
    const float* dc0 = (const float*)d_in[12];
    const float* dW1 = (const float*)d_in[13];
    const float* dU1 = (const float*)d_in[14];
    const float* db1 = (const float*)d_in[15];
    const float* dc1 = (const float*)d_in[16];
    float* out = (float*)d_out;

    const int SMEM = E_TOT * 4;   // 220928 B

    static bool attr_done = false;
    if (!attr_done) {
        cudaFuncSetAttribute(lstm_persist, cudaFuncAttributeMaxDynamicSharedMemorySize, SMEM);
        attr_done = true;
    }

    init_state_kernel<<<128, 512>>>();
    lstm_persist<<<128, 512, SMEM>>>(x, eW0, eU0, eb0, ec0, eW1, eU1, eb1, ec1,
                                     dW0, dU0, db0, dc0, dW1, dU1, db1, dc1, out);
}